// round 1
// baseline (speedup 1.0000x reference)
#include <cuda_runtime.h>
#include <math.h>

// Problem constants
#define B_   32
#define F_   128
#define T_   4000
#define H_   256     // hidden
#define O_   512     // 4F
#define KDIM 256     // 2F
#define EPS  1e-6f

// Scan chunking: 32 chunks of 125 -> 4000
#define CHUNK 125
#define NC    32

// GEMM tiling
#define BM 128
#define BN 64
#define BK 16
#define ASTR 132   // padded A-tile row stride (floats), keeps 16B alignment, breaks conflicts

// ---------------------------------------------------------------------------
// Scratch (device globals: no allocation allowed in kernel_launch)
// ---------------------------------------------------------------------------
__device__ float g_h  [B_ * T_ * H_];   // [b*T+t][H]      131 MB
__device__ float g_act[B_ * T_ * O_];   // [b*T+t][512]    262 MB, post-activation
__device__ float g_Ac [B_ * F_ * NC];
__device__ float g_Bc [B_ * F_ * NC];
__device__ float g_Ms [B_ * F_ * NC];

// ---------------------------------------------------------------------------
// Activations
// ---------------------------------------------------------------------------
__device__ __forceinline__ float sigmoidf_(float v) {
    return 1.f / (1.f + expf(-v));
}
__device__ __forceinline__ float softplusf_(float v) {
    // numerically stable: log1p(exp(-|v|)) + max(v, 0)
    return log1pf(expf(-fabsf(v))) + fmaxf(v, 0.f);
}

// ---------------------------------------------------------------------------
// GEMM1: h[b,t,:] = relu( concat(X[b,:,t-1], X[b,:,t]) @ W1 + b1 )
//   A tile built on the fly from X (feature-major, coalesced along t)
// ---------------------------------------------------------------------------
__global__ __launch_bounds__(256) void gemm1_kernel(
    const float* __restrict__ X,
    const float* __restrict__ W1,
    const float* __restrict__ b1)
{
    __shared__ float As[BK * ASTR];
    __shared__ float Bs[BK * BN];

    const int b  = blockIdx.z;
    const int t0 = blockIdx.x * BM;
    const int n0 = blockIdx.y * BN;
    const int tid = threadIdx.x;
    const int tx = tid & 15;       // 16 -> N dir (x4)
    const int ty = tid >> 4;       // 16 -> M dir (x8)

    const float* Xb = X + b * (F_ * T_);

    float acc[8][4];
    #pragma unroll
    for (int i = 0; i < 8; i++)
        #pragma unroll
        for (int j = 0; j < 4; j++) acc[i][j] = 0.f;

    for (int k0 = 0; k0 < KDIM; k0 += BK) {
        // Load A tile: As[k][m] = inp[b, k0+k, t0+m]
        #pragma unroll
        for (int i = 0; i < 8; i++) {
            int idx = tid + i * 256;
            int k = idx >> 7;          // 0..15
            int m = idx & 127;
            int kk = k0 + k;
            int t  = t0 + m;
            float v = 0.f;
            if (t < T_) {
                if (kk < F_) {
                    int tp = (t == 0) ? 0 : (t - 1);
                    v = Xb[kk * T_ + tp];
                } else {
                    v = Xb[(kk - F_) * T_ + t];
                }
            }
            As[k * ASTR + m] = v;
        }
        // Load B tile: Bs[k][n] = W1[k0+k, n0+n]
        #pragma unroll
        for (int i = 0; i < 4; i++) {
            int idx = tid + i * 256;
            int k = idx >> 6;
            int n = idx & 63;
            Bs[k * BN + n] = W1[(k0 + k) * H_ + (n0 + n)];
        }
        __syncthreads();

        #pragma unroll
        for (int k = 0; k < BK; k++) {
            float4 a0 = *(const float4*)&As[k * ASTR + ty * 8];
            float4 a1 = *(const float4*)&As[k * ASTR + ty * 8 + 4];
            float4 bv = *(const float4*)&Bs[k * BN + tx * 4];
            float a[8] = {a0.x, a0.y, a0.z, a0.w, a1.x, a1.y, a1.z, a1.w};
            float bb[4] = {bv.x, bv.y, bv.z, bv.w};
            #pragma unroll
            for (int i = 0; i < 8; i++)
                #pragma unroll
                for (int j = 0; j < 4; j++)
                    acc[i][j] += a[i] * bb[j];
        }
        __syncthreads();
    }

    // Epilogue: bias + relu, vectorized store
    const int nbase = n0 + tx * 4;
    float4 bias = *(const float4*)&b1[nbase];
    float bb4[4] = {bias.x, bias.y, bias.z, bias.w};
    #pragma unroll
    for (int i = 0; i < 8; i++) {
        int t = t0 + ty * 8 + i;
        if (t >= T_) continue;
        int row = (b * T_ + t) * H_;
        float4 v;
        v.x = fmaxf(acc[i][0] + bb4[0], 0.f);
        v.y = fmaxf(acc[i][1] + bb4[1], 0.f);
        v.z = fmaxf(acc[i][2] + bb4[2], 0.f);
        v.w = fmaxf(acc[i][3] + bb4[3], 0.f);
        *(float4*)&g_h[row + nbase] = v;
    }
}

// ---------------------------------------------------------------------------
// GEMM2: act[m,:] = activation( h[m,:] @ W2 + b2 )
//   columns [0,256) and [384,512): sigmoid; [256,384): softplus
// ---------------------------------------------------------------------------
__global__ __launch_bounds__(256) void gemm2_kernel(
    const float* __restrict__ W2,
    const float* __restrict__ b2)
{
    __shared__ float As[BK * ASTR];
    __shared__ float Bs[BK * BN];

    const int m0 = blockIdx.x * BM;       // 128000 = 1000*128 exactly
    const int n0 = blockIdx.y * BN;
    const int tid = threadIdx.x;
    const int tx = tid & 15;
    const int ty = tid >> 4;

    float acc[8][4];
    #pragma unroll
    for (int i = 0; i < 8; i++)
        #pragma unroll
        for (int j = 0; j < 4; j++) acc[i][j] = 0.f;

    for (int k0 = 0; k0 < H_; k0 += BK) {
        // Load A tile (row-major h, transpose into As[k][m])
        #pragma unroll
        for (int i = 0; i < 8; i++) {
            int idx = tid + i * 256;
            int m = idx >> 4;          // 0..127
            int k = idx & 15;
            As[k * ASTR + m] = g_h[(m0 + m) * H_ + (k0 + k)];
        }
        #pragma unroll
        for (int i = 0; i < 4; i++) {
            int idx = tid + i * 256;
            int k = idx >> 6;
            int n = idx & 63;
            Bs[k * BN + n] = W2[(k0 + k) * O_ + (n0 + n)];
        }
        __syncthreads();

        #pragma unroll
        for (int k = 0; k < BK; k++) {
            float4 a0 = *(const float4*)&As[k * ASTR + ty * 8];
            float4 a1 = *(const float4*)&As[k * ASTR + ty * 8 + 4];
            float4 bv = *(const float4*)&Bs[k * BN + tx * 4];
            float a[8] = {a0.x, a0.y, a0.z, a0.w, a1.x, a1.y, a1.z, a1.w};
            float bb[4] = {bv.x, bv.y, bv.z, bv.w};
            #pragma unroll
            for (int i = 0; i < 8; i++)
                #pragma unroll
                for (int j = 0; j < 4; j++)
                    acc[i][j] += a[i] * bb[j];
        }
        __syncthreads();
    }

    const bool is_softplus = (n0 >= 256 && n0 < 384);   // BN=64 tiles never straddle groups
    const int nbase = n0 + tx * 4;
    float4 bias = *(const float4*)&b2[nbase];
    float bb4[4] = {bias.x, bias.y, bias.z, bias.w};
    #pragma unroll
    for (int i = 0; i < 8; i++) {
        int m = m0 + ty * 8 + i;
        int row = m * O_;
        float v[4];
        #pragma unroll
        for (int j = 0; j < 4; j++) {
            float u = acc[i][j] + bb4[j];
            v[j] = is_softplus ? softplusf_(u) : sigmoidf_(u);
        }
        float4 vv = {v[0], v[1], v[2], v[3]};
        *(float4*)&g_act[row + nbase] = vv;
    }
}

// ---------------------------------------------------------------------------
// Scan stage A: per-chunk composition  M_end = A*M_in + Bv
//   thread id = (b*NC + c)*F + f  -> consecutive threads = consecutive f (coalesced on g_act)
// ---------------------------------------------------------------------------
__global__ __launch_bounds__(256) void scan_reduce_kernel(const float* __restrict__ X)
{
    int id = blockIdx.x * blockDim.x + threadIdx.x;
    int f = id & (F_ - 1);
    int c = (id >> 7) & (NC - 1);
    int b = id >> 12;                    // /(F_*NC)

    const float* actb = g_act + (b * T_) * O_;
    const float* Xr = X + (b * F_ + f) * T_;

    float A = 1.f, Bv = 0.f;
    int t0 = c * CHUNK;
    for (int t = t0; t < t0 + CHUNK; t++) {
        float s = actb[t * O_ + f];
        float x = Xr[t];
        float a = 1.f - s;
        A  *= a;
        Bv = a * Bv + s * x;
    }
    g_Ac[(b * F_ + f) * NC + c] = A;
    g_Bc[(b * F_ + f) * NC + c] = Bv;
}

// ---------------------------------------------------------------------------
// Scan stage B: sequential over the NC chunk summaries per (b,f) chain
// ---------------------------------------------------------------------------
__global__ __launch_bounds__(256) void scan_chain_kernel()
{
    int id = blockIdx.x * blockDim.x + threadIdx.x;   // 0 .. B*F-1
    float M = 0.f;
    int base = id * NC;
    #pragma unroll
    for (int c = 0; c < NC; c++) {
        g_Ms[base + c] = M;
        M = g_Ac[base + c] * M + g_Bc[base + c];
    }
}

// ---------------------------------------------------------------------------
// Scan stage C: replay recurrence per chunk + PCEN elementwise epilogue
// ---------------------------------------------------------------------------
__global__ __launch_bounds__(256) void scan_final_kernel(
    const float* __restrict__ X, float* __restrict__ out)
{
    int id = blockIdx.x * blockDim.x + threadIdx.x;
    int f = id & (F_ - 1);
    int c = (id >> 7) & (NC - 1);
    int b = id >> 12;

    const float* actb = g_act + (b * T_) * O_;
    const float* Xr = X + (b * F_ + f) * T_;
    float* Or = out + (b * F_ + f) * T_;

    float M = g_Ms[(b * F_ + f) * NC + c];
    int t0 = c * CHUNK;
    for (int t = t0; t < t0 + CHUNK; t++) {
        const float* rowp = actb + t * O_;
        float s     = rowp[f];
        float alpha = rowp[128 + f];
        float delta = rowp[256 + f];
        float r     = rowp[384 + f];
        float x = Xr[t];
        M = (1.f - s) * M + s * x;
        float base = x / powf(M + EPS, alpha) + delta;
        Or[t] = powf(base, r) - powf(delta, r);
    }
}

// ---------------------------------------------------------------------------
// Launch
// ---------------------------------------------------------------------------
extern "C" void kernel_launch(void* const* d_in, const int* in_sizes, int n_in,
                              void* d_out, int out_size)
{
    const float* X  = (const float*)d_in[0];
    const float* W1 = (const float*)d_in[1];
    const float* b1 = (const float*)d_in[2];
    const float* W2 = (const float*)d_in[3];
    const float* b2 = (const float*)d_in[4];
    float* out = (float*)d_out;

    dim3 g1((T_ + BM - 1) / BM, H_ / BN, B_);        // 32 x 4 x 32
    gemm1_kernel<<<g1, 256>>>(X, W1, b1);

    dim3 g2((B_ * T_) / BM, O_ / BN);                // 1000 x 8
    gemm2_kernel<<<g2, 256>>>(W2, b2);

    scan_reduce_kernel<<<(B_ * F_ * NC) / 256, 256>>>(X);
    scan_chain_kernel<<<(B_ * F_) / 256, 256>>>();
    scan_final_kernel<<<(B_ * F_ * NC) / 256, 256>>>(X, out);
}

// round 3
// speedup vs baseline: 2.2228x; 2.2228x over previous
#include <cuda_runtime.h>
#include <cuda_bf16.h>
#include <math.h>
#include <stdint.h>

// Problem constants
#define B_   32
#define F_   128
#define T_   4000
#define H_   256     // hidden
#define O_   512     // 4F
#define KDIM 256     // 2F
#define EPS  1e-6f

// Scan chunking: 32 chunks of 125 -> 4000
#define CHUNK 125
#define NC    32

// GEMM tiling
#define BM 128
#define BN 128
#define BK 32
#define ROWB 80          // bytes per smem row (32 bf16 = 64B + 16B pad) -> conflict-free ldmatrix

// ---------------------------------------------------------------------------
// Scratch (device globals: no allocation allowed in kernel_launch)
// ---------------------------------------------------------------------------
__device__ float g_Xt [B_ * T_ * F_];   // [b][t][f]
__device__ float g_W1t[H_ * KDIM];      // [n][k]
__device__ float g_W2t[O_ * KDIM];      // [n][k]
__device__ float g_h  [B_ * T_ * H_];   // [b*T+t][H]
__device__ float g_act[B_ * T_ * O_];   // [b*T+t][512]
__device__ float g_Ac [B_ * F_ * NC];
__device__ float g_Bc [B_ * F_ * NC];
__device__ float g_Ms [B_ * F_ * NC];

// ---------------------------------------------------------------------------
// Helpers
// ---------------------------------------------------------------------------
__device__ __forceinline__ uint32_t smem_u32(const void* p) {
    uint32_t a;
    asm("{ .reg .u64 t; cvta.to.shared.u64 t, %1; cvt.u32.u64 %0, t; }" : "=r"(a) : "l"(p));
    return a;
}

__device__ __forceinline__ void ldsm_x4(uint32_t& r0, uint32_t& r1, uint32_t& r2, uint32_t& r3,
                                        uint32_t addr) {
    asm volatile("ldmatrix.sync.aligned.m8n8.x4.shared.b16 {%0,%1,%2,%3}, [%4];"
                 : "=r"(r0), "=r"(r1), "=r"(r2), "=r"(r3) : "r"(addr));
}

__device__ __forceinline__ void mma_bf16(float* c, const uint32_t* a, const uint32_t* b) {
    asm volatile("mma.sync.aligned.m16n8k16.row.col.f32.bf16.bf16.f32 "
                 "{%0,%1,%2,%3}, {%4,%5,%6,%7}, {%8,%9}, {%0,%1,%2,%3};"
                 : "+f"(c[0]), "+f"(c[1]), "+f"(c[2]), "+f"(c[3])
                 : "r"(a[0]), "r"(a[1]), "r"(a[2]), "r"(a[3]), "r"(b[0]), "r"(b[1]));
}

__device__ __forceinline__ void cvt_hilo(float x, float y, uint32_t& hi, uint32_t& lo) {
    __nv_bfloat162 h = __floats2bfloat162_rn(x, y);
    float hx = __bfloat162float(h.x), hy = __bfloat162float(h.y);
    __nv_bfloat162 l = __floats2bfloat162_rn(x - hx, y - hy);
    hi = ((uint32_t)__bfloat16_as_ushort(h.y) << 16) | (uint32_t)__bfloat16_as_ushort(h.x);
    lo = ((uint32_t)__bfloat16_as_ushort(l.y) << 16) | (uint32_t)__bfloat16_as_ushort(l.x);
}

// stage 16 consecutive fp32 -> hi/lo bf16 smem at (row, half)
__device__ __forceinline__ void stage16(const float* __restrict__ src,
                                        char* __restrict__ hi, char* __restrict__ lo,
                                        int row, int half) {
    uint32_t off = (uint32_t)row * ROWB + (uint32_t)half * 32;
    #pragma unroll
    for (int q = 0; q < 4; q++) {
        float4 v = *(const float4*)(src + q * 4);
        uint32_t h0, l0, h1, l1;
        cvt_hilo(v.x, v.y, h0, l0);
        cvt_hilo(v.z, v.w, h1, l1);
        *(uint32_t*)(hi + off + q * 8)     = h0;
        *(uint32_t*)(hi + off + q * 8 + 4) = h1;
        *(uint32_t*)(lo + off + q * 8)     = l0;
        *(uint32_t*)(lo + off + q * 8 + 4) = l1;
    }
}

// ---------------------------------------------------------------------------
// Generic batched transpose: out[c][r] = in[r][c], in [R][C], batch z
// ---------------------------------------------------------------------------
__global__ void transpose_kernel(const float* __restrict__ in, float* __restrict__ out,
                                 int R, int C) {
    __shared__ float tile[32][33];
    size_t boff = (size_t)blockIdx.z * R * C;
    in += boff; out += boff;
    int c0 = blockIdx.x * 32, r0 = blockIdx.y * 32;
    int x = threadIdx.x, y = threadIdx.y;
    #pragma unroll
    for (int i = 0; i < 32; i += 8)
        tile[y + i][x] = in[(size_t)(r0 + y + i) * C + c0 + x];
    __syncthreads();
    #pragma unroll
    for (int i = 0; i < 32; i += 8)
        out[(size_t)(c0 + y + i) * R + r0 + x] = tile[x][y + i];
}

// ---------------------------------------------------------------------------
// GEMM via mma.sync, bf16 hi/lo split (3 products), fp32 accum.
// MODE 1: h = relu(concat(X[:,t-1],X[:,t]) @ W1 + b1)    [128000 x 256]
// MODE 2: act = activation(h @ W2 + b2)                   [128000 x 512]
// grid: (N/BN, 128000/BM); block 256 (8 warps, warp tile 64x32)
// ---------------------------------------------------------------------------
template<int MODE>
__global__ __launch_bounds__(256, 2) void gemm_mma(const float* __restrict__ bias) {
    __shared__ __align__(128) char sm[4 * BM * ROWB];   // 40960 B
    char* Ah = sm;
    char* Al = sm + BM * ROWB;
    char* Bh = sm + 2 * BM * ROWB;
    char* Bl = sm + 3 * BM * ROWB;
    const uint32_t sAh = smem_u32(Ah), sAl = smem_u32(Al);
    const uint32_t sBh = smem_u32(Bh), sBl = smem_u32(Bl);

    const int tid = threadIdx.x;
    const int lane = tid & 31;
    const int wid = tid >> 5;
    const int wm = wid >> 2;        // 0..1
    const int wn = wid & 3;         // 0..3
    const int n0 = blockIdx.x * BN;
    const int m0 = blockIdx.y * BM;

    float acc[4][4][4];
    #pragma unroll
    for (int i = 0; i < 4; i++)
        #pragma unroll
        for (int j = 0; j < 4; j++)
            #pragma unroll
            for (int q = 0; q < 4; q++) acc[i][j][q] = 0.f;

    const int srow = tid >> 1, shalf = tid & 1;

    // precompute ldmatrix lane-address components
    const uint32_t a_row  = (uint32_t)(wm * 64) + (lane & 15);
    const uint32_t a_colb = (uint32_t)(lane >> 4) * 16;
    const uint32_t b_row  = (uint32_t)(wn * 32) + ((lane >> 4) << 3) + (lane & 7);
    const uint32_t b_colb = ((uint32_t)(lane >> 3) & 1) * 16;

    #pragma unroll 1
    for (int k0 = 0; k0 < KDIM; k0 += BK) {
        // ---- stage A ----
        const float* asrc;
        if (MODE == 1) {
            int gr = m0 + srow;
            int b = gr / T_;
            int t = gr - b * T_;
            int col = k0 + shalf * 16;
            int tt, cc;
            if (col < 128) { tt = (t == 0) ? 0 : (t - 1); cc = col; }
            else           { tt = t; cc = col - 128; }
            asrc = g_Xt + ((size_t)b * T_ + tt) * F_ + cc;
        } else {
            asrc = g_h + (size_t)(m0 + srow) * H_ + k0 + shalf * 16;
        }
        stage16(asrc, Ah, Al, srow, shalf);
        // ---- stage B ----
        const float* wsrc = (MODE == 1 ? g_W1t : g_W2t)
                          + (size_t)(n0 + srow) * KDIM + k0 + shalf * 16;
        stage16(wsrc, Bh, Bl, srow, shalf);
        __syncthreads();

        #pragma unroll
        for (int s = 0; s < 2; s++) {
            // B fragments: 4 n-frags of 8, hi and lo
            uint32_t bh[4][2], bl[4][2];
            #pragma unroll
            for (int jj = 0; jj < 2; jj++) {
                uint32_t off = (b_row + jj * 16) * ROWB + b_colb + s * 32;
                uint32_t r0, r1, r2, r3;
                ldsm_x4(r0, r1, r2, r3, sBh + off);
                bh[2 * jj][0] = r0; bh[2 * jj][1] = r1;
                bh[2 * jj + 1][0] = r2; bh[2 * jj + 1][1] = r3;
                ldsm_x4(r0, r1, r2, r3, sBl + off);
                bl[2 * jj][0] = r0; bl[2 * jj][1] = r1;
                bl[2 * jj + 1][0] = r2; bl[2 * jj + 1][1] = r3;
            }
            #pragma unroll
            for (int i = 0; i < 4; i++) {
                uint32_t off = (a_row + i * 16) * ROWB + a_colb + s * 32;
                uint32_t ah[4], al[4];
                ldsm_x4(ah[0], ah[1], ah[2], ah[3], sAh + off);
                ldsm_x4(al[0], al[1], al[2], al[3], sAl + off);
                #pragma unroll
                for (int j = 0; j < 4; j++) {
                    mma_bf16(acc[i][j], ah, bh[j]);
                    mma_bf16(acc[i][j], ah, bl[j]);
                    mma_bf16(acc[i][j], al, bh[j]);
                }
            }
        }
        __syncthreads();
    }

    // ---- epilogue ----
    const int rloc = lane >> 2;
    const int cpair = (lane & 3) * 2;
    #pragma unroll
    for (int i = 0; i < 4; i++) {
        int r0 = m0 + wm * 64 + i * 16 + rloc;
        int r1 = r0 + 8;
        #pragma unroll
        for (int j = 0; j < 4; j++) {
            int nc = wn * 32 + j * 8 + cpair;        // local col in [0,128)
            int ng = n0 + nc;                        // global col
            float2 bb = *(const float2*)&bias[ng];
            float u0 = acc[i][j][0] + bb.x, u1 = acc[i][j][1] + bb.y;
            float u2 = acc[i][j][2] + bb.x, u3 = acc[i][j][3] + bb.y;
            if (MODE == 1) {
                float2 v0 = {fmaxf(u0, 0.f), fmaxf(u1, 0.f)};
                float2 v1 = {fmaxf(u2, 0.f), fmaxf(u3, 0.f)};
                *(float2*)&g_h[(size_t)r0 * H_ + ng] = v0;
                *(float2*)&g_h[(size_t)r1 * H_ + ng] = v1;
            } else {
                bool sp = (blockIdx.x == 2);   // cols [256,384): softplus (delta)
                float v[4];
                float uu[4] = {u0, u1, u2, u3};
                #pragma unroll
                for (int q = 0; q < 4; q++) {
                    float u = uu[q];
                    v[q] = sp ? (__logf(1.f + __expf(-fabsf(u))) + fmaxf(u, 0.f))
                              : (1.f / (1.f + __expf(-u)));
                }
                float2 v0 = {v[0], v[1]}, v1 = {v[2], v[3]};
                *(float2*)&g_act[(size_t)r0 * O_ + ng] = v0;
                *(float2*)&g_act[(size_t)r1 * O_ + ng] = v1;
            }
        }
    }
}

// ---------------------------------------------------------------------------
// Scan stage A: per-chunk composition  M_end = A*M_in + Bv
// ---------------------------------------------------------------------------
__global__ __launch_bounds__(256) void scan_reduce_kernel() {
    int id = blockIdx.x * blockDim.x + threadIdx.x;
    int f = id & (F_ - 1);
    int c = (id >> 7) & (NC - 1);
    int b = id >> 12;

    const float* actb = g_act + (size_t)(b * T_) * O_;
    const float* Xtb  = g_Xt + (size_t)b * T_ * F_;

    float A = 1.f, Bv = 0.f;
    int t0 = c * CHUNK;
    for (int t = t0; t < t0 + CHUNK; t++) {
        float s = actb[(size_t)t * O_ + f];
        float x = Xtb[(size_t)t * F_ + f];
        float a = 1.f - s;
        A  *= a;
        Bv = a * Bv + s * x;
    }
    g_Ac[(b * F_ + f) * NC + c] = A;
    g_Bc[(b * F_ + f) * NC + c] = Bv;
}

// ---------------------------------------------------------------------------
// Scan stage B: sequential over the NC chunk summaries
// ---------------------------------------------------------------------------
__global__ __launch_bounds__(256) void scan_chain_kernel() {
    int id = blockIdx.x * blockDim.x + threadIdx.x;   // 0 .. B*F-1
    float M = 0.f;
    int base = id * NC;
    #pragma unroll
    for (int c = 0; c < NC; c++) {
        g_Ms[base + c] = M;
        M = g_Ac[base + c] * M + g_Bc[base + c];
    }
}

// ---------------------------------------------------------------------------
// Scan stage C: replay recurrence + PCEN epilogue
// ---------------------------------------------------------------------------
__global__ __launch_bounds__(256) void scan_final_kernel(float* __restrict__ out) {
    int id = blockIdx.x * blockDim.x + threadIdx.x;
    int f = id & (F_ - 1);
    int c = (id >> 7) & (NC - 1);
    int b = id >> 12;

    const float* actb = g_act + (size_t)(b * T_) * O_;
    const float* Xtb  = g_Xt + (size_t)b * T_ * F_;
    float* Or = out + (size_t)(b * F_ + f) * T_;

    float M = g_Ms[(b * F_ + f) * NC + c];
    int t0 = c * CHUNK;
    for (int t = t0; t < t0 + CHUNK; t++) {
        const float* rowp = actb + (size_t)t * O_;
        float s     = rowp[f];
        float alpha = rowp[128 + f];
        float delta = rowp[256 + f];
        float r     = rowp[384 + f];
        float x = Xtb[(size_t)t * F_ + f];
        M = (1.f - s) * M + s * x;
        float base = x / __powf(M + EPS, alpha) + delta;
        Or[t] = __powf(base, r) - __powf(delta, r);
    }
}

// ---------------------------------------------------------------------------
// Launch
// ---------------------------------------------------------------------------
extern "C" void kernel_launch(void* const* d_in, const int* in_sizes, int n_in,
                              void* d_out, int out_size) {
    const float* X  = (const float*)d_in[0];
    const float* W1 = (const float*)d_in[1];
    const float* b1 = (const float*)d_in[2];
    const float* W2 = (const float*)d_in[3];
    const float* b2 = (const float*)d_in[4];
    float* out = (float*)d_out;

    float* Xt;  cudaGetSymbolAddress((void**)&Xt,  g_Xt);
    float* W1t; cudaGetSymbolAddress((void**)&W1t, g_W1t);
    float* W2t; cudaGetSymbolAddress((void**)&W2t, g_W2t);

    // X [F][T] -> Xt [T][F] per batch; W1 [K][H] -> W1t [H][K]; W2 [K][O] -> W2t [O][K]
    transpose_kernel<<<dim3(T_ / 32, F_ / 32, B_), dim3(32, 8)>>>(X, Xt, F_, T_);
    transpose_kernel<<<dim3(H_ / 32, KDIM / 32, 1), dim3(32, 8)>>>(W1, W1t, KDIM, H_);
    transpose_kernel<<<dim3(O_ / 32, KDIM / 32, 1), dim3(32, 8)>>>(W2, W2t, KDIM, O_);

    gemm_mma<1><<<dim3(H_ / BN, (B_ * T_) / BM), 256>>>(b1);   // (2, 1000)
    gemm_mma<2><<<dim3(O_ / BN, (B_ * T_) / BM), 256>>>(b2);   // (4, 1000)

    scan_reduce_kernel<<<(B_ * F_ * NC) / 256, 256>>>();
    scan_chain_kernel<<<(B_ * F_) / 256, 256>>>();
    scan_final_kernel<<<(B_ * F_ * NC) / 256, 256>>>(out);
}

// round 6
// speedup vs baseline: 2.8022x; 1.2607x over previous
#include <cuda_runtime.h>
#include <cuda_bf16.h>
#include <math.h>
#include <stdint.h>

// Problem constants
#define B_   32
#define F_   128
#define T_   4000
#define H_   256     // hidden
#define O_   512     // 4F
#define KDIM 256     // 2F
#define EPS  1e-6f

// Scan chunking: 32 chunks of 125 -> 4000
#define CHUNK 125
#define NC    32

// GEMM tiling
#define BM 128
#define BN 128
#define BK 32
#define ROWB 80                   // smem row stride bytes (64B data + 16B pad)
#define PL   (BM * ROWB)          // one plane: 10240 B
#define SSTR (4 * PL)             // one stage (Ah,Al,Bh,Bl): 40960 B
#define SMEM_GEMM (2 * SSTR)      // 81920 B

// ---------------------------------------------------------------------------
// Scratch (device globals)
// ---------------------------------------------------------------------------
__device__ __align__(128) float          g_Xt [B_ * T_ * F_];
__device__ __align__(128) __nv_bfloat16  g_Xh [B_ * T_ * F_];
__device__ __align__(128) __nv_bfloat16  g_Xl [B_ * T_ * F_];
__device__ __align__(128) __nv_bfloat16  g_W1h[H_ * KDIM];
__device__ __align__(128) __nv_bfloat16  g_W1l[H_ * KDIM];
__device__ __align__(128) __nv_bfloat16  g_W2h[O_ * KDIM];
__device__ __align__(128) __nv_bfloat16  g_W2l[O_ * KDIM];
__device__ __align__(128) __nv_bfloat16  g_Hh [B_ * T_ * H_];
__device__ __align__(128) __nv_bfloat16  g_Hl [B_ * T_ * H_];
__device__ __align__(128) float          g_act[B_ * T_ * O_];
__device__ float g_Ac[B_ * NC * F_];    // [b][c][f]
__device__ float g_Bc[B_ * NC * F_];
__device__ float g_Ms[B_ * NC * F_];

// ---------------------------------------------------------------------------
// Helpers
// ---------------------------------------------------------------------------
__device__ __forceinline__ uint32_t smem_u32(const void* p) {
    uint32_t a;
    asm("{ .reg .u64 t; cvta.to.shared.u64 t, %1; cvt.u32.u64 %0, t; }" : "=r"(a) : "l"(p));
    return a;
}
__device__ __forceinline__ void cp16(uint32_t dst, const void* src) {
    asm volatile("cp.async.cg.shared.global [%0], [%1], 16;" :: "r"(dst), "l"(src) : "memory");
}
#define CP_COMMIT() asm volatile("cp.async.commit_group;" ::: "memory")
#define CP_WAIT1()  asm volatile("cp.async.wait_group 1;" ::: "memory")

__device__ __forceinline__ void ldsm_x4(uint32_t& r0, uint32_t& r1, uint32_t& r2, uint32_t& r3,
                                        uint32_t addr) {
    asm volatile("ldmatrix.sync.aligned.m8n8.x4.shared.b16 {%0,%1,%2,%3}, [%4];"
                 : "=r"(r0), "=r"(r1), "=r"(r2), "=r"(r3) : "r"(addr));
}
__device__ __forceinline__ void mma_bf16(float* c, const uint32_t* a, const uint32_t* b) {
    asm volatile("mma.sync.aligned.m16n8k16.row.col.f32.bf16.bf16.f32 "
                 "{%0,%1,%2,%3}, {%4,%5,%6,%7}, {%8,%9}, {%0,%1,%2,%3};"
                 : "+f"(c[0]), "+f"(c[1]), "+f"(c[2]), "+f"(c[3])
                 : "r"(a[0]), "r"(a[1]), "r"(a[2]), "r"(a[3]), "r"(b[0]), "r"(b[1]));
}
__device__ __forceinline__ void cvt_hilo(float x, float y, uint32_t& hi, uint32_t& lo) {
    __nv_bfloat162 h = __floats2bfloat162_rn(x, y);
    float hx = __bfloat162float(h.x), hy = __bfloat162float(h.y);
    __nv_bfloat162 l = __floats2bfloat162_rn(x - hx, y - hy);
    hi = ((uint32_t)__bfloat16_as_ushort(h.y) << 16) | (uint32_t)__bfloat16_as_ushort(h.x);
    lo = ((uint32_t)__bfloat16_as_ushort(l.y) << 16) | (uint32_t)__bfloat16_as_ushort(l.x);
}

// ---------------------------------------------------------------------------
// Transpose + hi/lo bf16 convert: in [R][C] fp32 -> out [C][R] (fp32 optional, hi, lo)
// ---------------------------------------------------------------------------
__global__ void transpose_conv(const float* __restrict__ in, float* __restrict__ outF,
                               __nv_bfloat16* __restrict__ outH, __nv_bfloat16* __restrict__ outL,
                               int R, int C) {
    __shared__ float tile[32][33];
    size_t boff = (size_t)blockIdx.z * R * C;
    in += boff;
    int c0 = blockIdx.x * 32, r0 = blockIdx.y * 32;
    int x = threadIdx.x, y = threadIdx.y;
    #pragma unroll
    for (int i = 0; i < 32; i += 8)
        tile[y + i][x] = in[(size_t)(r0 + y + i) * C + c0 + x];
    __syncthreads();
    #pragma unroll
    for (int i = 0; i < 32; i += 8) {
        float v = tile[x][y + i];
        size_t idx = boff + (size_t)(c0 + y + i) * R + r0 + x;
        if (outF) outF[idx] = v;
        __nv_bfloat16 h = __float2bfloat16(v);
        outH[idx] = h;
        outL[idx] = __float2bfloat16(v - __bfloat162float(h));
    }
}

// ---------------------------------------------------------------------------
// GEMM via mma.sync, pre-split bf16 hi/lo operands, cp.async double buffer.
// MODE 1: Hh/Hl = relu(concat(X[:,t-1],X[:,t]) @ W1 + b1)  [128000 x 256]
// MODE 2: act   = activation(h @ W2 + b2)                  [128000 x 512]
// ---------------------------------------------------------------------------
template<int MODE>
__global__ __launch_bounds__(256, 2) void gemm_mma(const float* __restrict__ bias) {
    extern __shared__ __align__(128) char sm[];
    const int tid = threadIdx.x;
    const int lane = tid & 31;
    const int wid = tid >> 5;
    const int wm = wid >> 2;
    const int wn = wid & 3;
    const int n0 = blockIdx.x * BN;
    const int m0 = blockIdx.y * BM;

    const uint32_t smbase = smem_u32(sm);

    // staging descriptors: thread -> (row0 + it*64, seg)
    const int seg  = tid & 3;
    const int row0 = tid >> 2;

    const __nv_bfloat16* AH = (MODE == 1) ? g_Xh : g_Hh;
    const __nv_bfloat16* AL = (MODE == 1) ? g_Xl : g_Hl;
    const __nv_bfloat16* WH = (MODE == 1) ? g_W1h : g_W2h;
    const __nv_bfloat16* WL = (MODE == 1) ? g_W1l : g_W2l;

    size_t acur[2], aprev[2], boff[2];
    #pragma unroll
    for (int it = 0; it < 2; it++) {
        int row = row0 + it * 64;
        if (MODE == 1) {
            int gr = m0 + row;
            int b = gr / T_;
            int t = gr - b * T_;
            int tp = t ? (t - 1) : 0;
            acur[it]  = ((size_t)b * T_ + t)  * F_ + seg * 8;
            aprev[it] = ((size_t)b * T_ + tp) * F_ + seg * 8;
        } else {
            acur[it] = (size_t)(m0 + row) * H_ + seg * 8;
        }
        boff[it] = (size_t)(n0 + row) * KDIM + seg * 8;
    }

    auto stage = [&](int c, int st) {
        const int k0 = c * BK;
        uint32_t sA  = smbase + st * SSTR;
        #pragma unroll
        for (int it = 0; it < 2; it++) {
            int row = row0 + it * 64;
            uint32_t d = (uint32_t)row * ROWB + seg * 16;
            size_t so;
            if (MODE == 1) so = (k0 < 128) ? (aprev[it] + k0) : (acur[it] + (k0 - 128));
            else           so = acur[it] + k0;
            cp16(sA + d,          AH + so);
            cp16(sA + PL + d,     AL + so);
            size_t bo = boff[it] + k0;
            cp16(sA + 2 * PL + d, WH + bo);
            cp16(sA + 3 * PL + d, WL + bo);
        }
    };

    float acc[4][4][4];
    #pragma unroll
    for (int i = 0; i < 4; i++)
        #pragma unroll
        for (int j = 0; j < 4; j++)
            #pragma unroll
            for (int q = 0; q < 4; q++) acc[i][j][q] = 0.f;

    const uint32_t a_row  = (uint32_t)(wm * 64) + (lane & 15);
    const uint32_t a_colb = (uint32_t)(lane >> 4) * 16;
    const uint32_t b_row  = (uint32_t)(wn * 32) + ((lane >> 4) << 3) + (lane & 7);
    const uint32_t b_colb = ((uint32_t)(lane >> 3) & 1) * 16;

    stage(0, 0); CP_COMMIT();
    stage(1, 1); CP_COMMIT();

    #pragma unroll 1
    for (int c = 0; c < KDIM / BK; c++) {
        CP_WAIT1();
        __syncthreads();
        const int st = c & 1;
        const uint32_t sAh = smbase + st * SSTR;
        const uint32_t sAl = sAh + PL;
        const uint32_t sBh = sAh + 2 * PL;
        const uint32_t sBl = sAh + 3 * PL;

        #pragma unroll
        for (int s = 0; s < 2; s++) {
            uint32_t bh[4][2], bl[4][2];
            #pragma unroll
            for (int jj = 0; jj < 2; jj++) {
                uint32_t off = (b_row + jj * 16) * ROWB + b_colb + s * 32;
                uint32_t r0, r1, r2, r3;
                ldsm_x4(r0, r1, r2, r3, sBh + off);
                bh[2 * jj][0] = r0; bh[2 * jj][1] = r1;
                bh[2 * jj + 1][0] = r2; bh[2 * jj + 1][1] = r3;
                ldsm_x4(r0, r1, r2, r3, sBl + off);
                bl[2 * jj][0] = r0; bl[2 * jj][1] = r1;
                bl[2 * jj + 1][0] = r2; bl[2 * jj + 1][1] = r3;
            }
            #pragma unroll
            for (int i = 0; i < 4; i++) {
                uint32_t off = (a_row + i * 16) * ROWB + a_colb + s * 32;
                uint32_t ah[4], al[4];
                ldsm_x4(ah[0], ah[1], ah[2], ah[3], sAh + off);
                ldsm_x4(al[0], al[1], al[2], al[3], sAl + off);
                #pragma unroll
                for (int j = 0; j < 4; j++) {
                    mma_bf16(acc[i][j], ah, bh[j]);
                    mma_bf16(acc[i][j], ah, bl[j]);
                    mma_bf16(acc[i][j], al, bh[j]);
                }
            }
        }
        __syncthreads();
        if (c + 2 < KDIM / BK) stage(c + 2, st);
        CP_COMMIT();
    }

    // ---- epilogue ----
    const int rloc = lane >> 2;
    const int cpair = (lane & 3) * 2;
    #pragma unroll
    for (int i = 0; i < 4; i++) {
        int r0 = m0 + wm * 64 + i * 16 + rloc;
        int r1 = r0 + 8;
        #pragma unroll
        for (int j = 0; j < 4; j++) {
            int ng = n0 + wn * 32 + j * 8 + cpair;
            float2 bb = *(const float2*)&bias[ng];
            float u0 = acc[i][j][0] + bb.x, u1 = acc[i][j][1] + bb.y;
            float u2 = acc[i][j][2] + bb.x, u3 = acc[i][j][3] + bb.y;
            if (MODE == 1) {
                u0 = fmaxf(u0, 0.f); u1 = fmaxf(u1, 0.f);
                u2 = fmaxf(u2, 0.f); u3 = fmaxf(u3, 0.f);
                uint32_t h0, l0, h1, l1;
                cvt_hilo(u0, u1, h0, l0);
                cvt_hilo(u2, u3, h1, l1);
                *(uint32_t*)&g_Hh[(size_t)r0 * H_ + ng] = h0;
                *(uint32_t*)&g_Hl[(size_t)r0 * H_ + ng] = l0;
                *(uint32_t*)&g_Hh[(size_t)r1 * H_ + ng] = h1;
                *(uint32_t*)&g_Hl[(size_t)r1 * H_ + ng] = l1;
            } else {
                bool sp = (blockIdx.x == 2);   // cols [256,384): softplus (delta)
                float uu[4] = {u0, u1, u2, u3};
                float v[4];
                #pragma unroll
                for (int q = 0; q < 4; q++) {
                    float u = uu[q];
                    v[q] = sp ? (__logf(1.f + __expf(-fabsf(u))) + fmaxf(u, 0.f))
                              : (1.f / (1.f + __expf(-u)));
                }
                float2 v0 = {v[0], v[1]}, v1 = {v[2], v[3]};
                *(float2*)&g_act[(size_t)r0 * O_ + ng] = v0;
                *(float2*)&g_act[(size_t)r1 * O_ + ng] = v1;
            }
        }
    }
}

// ---------------------------------------------------------------------------
// Scan stage A: per-chunk composition  (writes [b][c][f], fully coalesced)
// ---------------------------------------------------------------------------
__global__ __launch_bounds__(256) void scan_reduce_kernel() {
    int id = blockIdx.x * blockDim.x + threadIdx.x;
    int f = id & (F_ - 1);
    int c = (id >> 7) & (NC - 1);
    int b = id >> 12;

    const float* actb = g_act + (size_t)(b * T_) * O_;
    const float* Xtb  = g_Xt + (size_t)b * T_ * F_;

    float A = 1.f, Bv = 0.f;
    int t0 = c * CHUNK;
    for (int t = t0; t < t0 + CHUNK; t++) {
        float s = actb[(size_t)t * O_ + f];
        float x = Xtb[(size_t)t * F_ + f];
        float a = 1.f - s;
        A  *= a;
        Bv = a * Bv + s * x;
    }
    g_Ac[id] = A;
    g_Bc[id] = Bv;
}

// ---------------------------------------------------------------------------
// Scan stage B: per-(b,f) chain over NC chunk summaries (coalesced over f)
// ---------------------------------------------------------------------------
__global__ __launch_bounds__(128) void scan_chain_kernel() {
    int b = blockIdx.x, f = threadIdx.x;
    float M = 0.f;
    #pragma unroll
    for (int c = 0; c < NC; c++) {
        int idx = (b * NC + c) * F_ + f;
        g_Ms[idx] = M;
        M = g_Ac[idx] * M + g_Bc[idx];
    }
}

// ---------------------------------------------------------------------------
// Scan stage C: replay + PCEN epilogue; smem transpose for coalesced output
// block = (b*NC + c), 128 threads = f
// ---------------------------------------------------------------------------
__global__ __launch_bounds__(128) void scan_final_kernel(float* __restrict__ out) {
    __shared__ float tile[32][129];
    int bc = blockIdx.x;
    int b = bc >> 5;           // /NC
    int c = bc & (NC - 1);
    int f = threadIdx.x;
    int lane = f & 31, wid = f >> 5;

    const float* actb = g_act + (size_t)(b * T_) * O_;
    const float* Xtb  = g_Xt + (size_t)b * T_ * F_;

    float M = g_Ms[bc * F_ + f];
    int t0 = c * CHUNK, t1 = t0 + CHUNK;
    for (int tb = t0; tb < t1; tb += 32) {
        int nrow = min(32, t1 - tb);
        for (int q = 0; q < nrow; q++) {
            int t = tb + q;
            const float* rowp = actb + (size_t)t * O_;
            float s     = rowp[f];
            float alpha = rowp[128 + f];
            float delta = rowp[256 + f];
            float r     = rowp[384 + f];
            float x = Xtb[(size_t)t * F_ + f];
            M = (1.f - s) * M + s * x;
            float base = x / __powf(M + EPS, alpha) + delta;
            tile[q][f] = __powf(base, r) - __powf(delta, r);
        }
        __syncthreads();
        #pragma unroll
        for (int ff = wid; ff < 128; ff += 4) {
            if (lane < nrow)
                out[(size_t)(b * F_ + ff) * T_ + tb + lane] = tile[lane][ff];
        }
        __syncthreads();
    }
}

// ---------------------------------------------------------------------------
// Launch
// ---------------------------------------------------------------------------
extern "C" void kernel_launch(void* const* d_in, const int* in_sizes, int n_in,
                              void* d_out, int out_size) {
    const float* X  = (const float*)d_in[0];
    const float* W1 = (const float*)d_in[1];
    const float* b1 = (const float*)d_in[2];
    const float* W2 = (const float*)d_in[3];
    const float* b2 = (const float*)d_in[4];
    float* out = (float*)d_out;

    float *Xt;
    __nv_bfloat16 *Xh, *Xl, *W1h, *W1l, *W2h, *W2l;
    cudaGetSymbolAddress((void**)&Xt,  g_Xt);
    cudaGetSymbolAddress((void**)&Xh,  g_Xh);
    cudaGetSymbolAddress((void**)&Xl,  g_Xl);
    cudaGetSymbolAddress((void**)&W1h, g_W1h);
    cudaGetSymbolAddress((void**)&W1l, g_W1l);
    cudaGetSymbolAddress((void**)&W2h, g_W2h);
    cudaGetSymbolAddress((void**)&W2l, g_W2l);

    // Idempotent host-side attribute set (no stream interaction; capture-safe)
    cudaFuncSetAttribute(gemm_mma<1>, cudaFuncAttributeMaxDynamicSharedMemorySize, SMEM_GEMM);
    cudaFuncSetAttribute(gemm_mma<2>, cudaFuncAttributeMaxDynamicSharedMemorySize, SMEM_GEMM);

    // X [F][T] per batch -> Xt/Xh/Xl [T][F]; W1 [K][H] -> [H][K]; W2 [K][O] -> [O][K]
    transpose_conv<<<dim3(T_ / 32, F_ / 32, B_), dim3(32, 8)>>>(X, Xt, Xh, Xl, F_, T_);
    transpose_conv<<<dim3(H_ / 32, KDIM / 32, 1), dim3(32, 8)>>>(W1, nullptr, W1h, W1l, KDIM, H_);
    transpose_conv<<<dim3(O_ / 32, KDIM / 32, 1), dim3(32, 8)>>>(W2, nullptr, W2h, W2l, KDIM, O_);

    gemm_mma<1><<<dim3(H_ / BN, (B_ * T_) / BM), 256, SMEM_GEMM>>>(b1);   // (2, 1000)
    gemm_mma<2><<<dim3(O_ / BN, (B_ * T_) / BM), 256, SMEM_GEMM>>>(b2);   // (4, 1000)

    scan_reduce_kernel<<<(B_ * F_ * NC) / 256, 256>>>();
    scan_chain_kernel<<<B_, 128>>>();
    scan_final_kernel<<<B_ * NC, 128>>>(out);
}

// round 7
// speedup vs baseline: 3.1309x; 1.1173x over previous
#include <cuda_runtime.h>
#include <cuda_bf16.h>
#include <math.h>
#include <stdint.h>

// Problem constants
#define B_   32
#define F_   128
#define T_   4000
#define H_   256     // hidden
#define O_   512     // 4F
#define KDIM 256     // 2F
#define EPS  1e-6f

// Scan chunking: 32 chunks of 125 -> 4000
#define CHUNK 125
#define NC    32

// GEMM tiling
#define BM 128
#define BN 128
#define BK 32
#define ROWB 64                   // smem row stride bytes (XOR swizzle, no pad)
#define PL   (BM * ROWB)          // one plane: 8192 B
#define SSTR (4 * PL)             // one stage (Ah,Al,Bh,Bl): 32768 B
#define NSTAGE 3
#define SMEM_GEMM (NSTAGE * SSTR) // 98304 B

// ---------------------------------------------------------------------------
// Scratch (device globals)
// ---------------------------------------------------------------------------
__device__ __align__(128) float          g_Xt [B_ * T_ * F_];
__device__ __align__(128) __nv_bfloat16  g_Xh [B_ * T_ * F_];
__device__ __align__(128) __nv_bfloat16  g_Xl [B_ * T_ * F_];
__device__ __align__(128) __nv_bfloat16  g_W1h[H_ * KDIM];
__device__ __align__(128) __nv_bfloat16  g_W1l[H_ * KDIM];
__device__ __align__(128) __nv_bfloat16  g_W2h[O_ * KDIM];
__device__ __align__(128) __nv_bfloat16  g_W2l[O_ * KDIM];
__device__ __align__(128) __nv_bfloat16  g_Hh [B_ * T_ * H_];
__device__ __align__(128) __nv_bfloat16  g_Hl [B_ * T_ * H_];
__device__ __align__(128) float          g_act[B_ * T_ * O_];
__device__ float g_Ac[B_ * NC * F_];    // [b][c][f]
__device__ float g_Bc[B_ * NC * F_];
__device__ float g_Ms[B_ * NC * F_];

// ---------------------------------------------------------------------------
// Helpers
// ---------------------------------------------------------------------------
__device__ __forceinline__ uint32_t smem_u32(const void* p) {
    uint32_t a;
    asm("{ .reg .u64 t; cvta.to.shared.u64 t, %1; cvt.u32.u64 %0, t; }" : "=r"(a) : "l"(p));
    return a;
}
__device__ __forceinline__ void cp16(uint32_t dst, const void* src) {
    asm volatile("cp.async.cg.shared.global [%0], [%1], 16;" :: "r"(dst), "l"(src) : "memory");
}
#define CP_COMMIT() asm volatile("cp.async.commit_group;" ::: "memory")
#define CP_WAIT1()  asm volatile("cp.async.wait_group 1;" ::: "memory")

__device__ __forceinline__ void ldsm_x4(uint32_t& r0, uint32_t& r1, uint32_t& r2, uint32_t& r3,
                                        uint32_t addr) {
    asm volatile("ldmatrix.sync.aligned.m8n8.x4.shared.b16 {%0,%1,%2,%3}, [%4];"
                 : "=r"(r0), "=r"(r1), "=r"(r2), "=r"(r3) : "r"(addr));
}
__device__ __forceinline__ void mma_bf16(float* c, const uint32_t* a, const uint32_t* b) {
    asm volatile("mma.sync.aligned.m16n8k16.row.col.f32.bf16.bf16.f32 "
                 "{%0,%1,%2,%3}, {%4,%5,%6,%7}, {%8,%9}, {%0,%1,%2,%3};"
                 : "+f"(c[0]), "+f"(c[1]), "+f"(c[2]), "+f"(c[3])
                 : "r"(a[0]), "r"(a[1]), "r"(a[2]), "r"(a[3]), "r"(b[0]), "r"(b[1]));
}
__device__ __forceinline__ void cvt_hilo(float x, float y, uint32_t& hi, uint32_t& lo) {
    __nv_bfloat162 h = __floats2bfloat162_rn(x, y);
    float hx = __bfloat162float(h.x), hy = __bfloat162float(h.y);
    __nv_bfloat162 l = __floats2bfloat162_rn(x - hx, y - hy);
    hi = ((uint32_t)__bfloat16_as_ushort(h.y) << 16) | (uint32_t)__bfloat16_as_ushort(h.x);
    lo = ((uint32_t)__bfloat16_as_ushort(l.y) << 16) | (uint32_t)__bfloat16_as_ushort(l.x);
}

// ---------------------------------------------------------------------------
// Transpose + hi/lo bf16 convert: in [R][C] fp32 -> out [C][R] (fp32 optional, hi, lo)
// ---------------------------------------------------------------------------
__global__ void transpose_conv(const float* __restrict__ in, float* __restrict__ outF,
                               __nv_bfloat16* __restrict__ outH, __nv_bfloat16* __restrict__ outL,
                               int R, int C) {
    __shared__ float tile[32][33];
    size_t boff = (size_t)blockIdx.z * R * C;
    in += boff;
    int c0 = blockIdx.x * 32, r0 = blockIdx.y * 32;
    int x = threadIdx.x, y = threadIdx.y;
    #pragma unroll
    for (int i = 0; i < 32; i += 8)
        tile[y + i][x] = in[(size_t)(r0 + y + i) * C + c0 + x];
    __syncthreads();
    #pragma unroll
    for (int i = 0; i < 32; i += 8) {
        float v = tile[x][y + i];
        size_t idx = boff + (size_t)(c0 + y + i) * R + r0 + x;
        if (outF) outF[idx] = v;
        __nv_bfloat16 h = __float2bfloat16(v);
        outH[idx] = h;
        outL[idx] = __float2bfloat16(v - __bfloat162float(h));
    }
}

// ---------------------------------------------------------------------------
// GEMM via mma.sync, pre-split bf16 hi/lo operands, 3-stage cp.async pipeline,
// XOR-swizzled smem (conflict-free ldmatrix, no padding), 1 barrier per chunk.
// MODE 1: Hh/Hl = relu(concat(X[:,t-1],X[:,t]) @ W1 + b1)  [128000 x 256]
// MODE 2: act   = activation(h @ W2 + b2)                  [128000 x 512]
// ---------------------------------------------------------------------------
template<int MODE>
__global__ __launch_bounds__(256, 2) void gemm_mma(const float* __restrict__ bias) {
    extern __shared__ __align__(128) char sm[];
    const int tid = threadIdx.x;
    const int lane = tid & 31;
    const int wid = tid >> 5;
    const int wm = wid >> 2;
    const int wn = wid & 3;
    const int n0 = blockIdx.x * BN;
    const int m0 = blockIdx.y * BM;

    const uint32_t smbase = smem_u32(sm);

    // staging: thread -> (row0 + it*64, seg); swizzle const across both rows
    const int seg  = tid & 3;
    const int row0 = tid >> 2;
    const uint32_t sw_st = ((uint32_t)row0 >> 1) & 3;
    const uint32_t st_d0 = (uint32_t)row0 * ROWB + ((seg ^ sw_st) << 4);

    const __nv_bfloat16* AH = (MODE == 1) ? g_Xh : g_Hh;
    const __nv_bfloat16* AL = (MODE == 1) ? g_Xl : g_Hl;
    const __nv_bfloat16* WH = (MODE == 1) ? g_W1h : g_W2h;
    const __nv_bfloat16* WL = (MODE == 1) ? g_W1l : g_W2l;

    size_t acur[2], aprev[2], boff[2];
    #pragma unroll
    for (int it = 0; it < 2; it++) {
        int row = row0 + it * 64;
        if (MODE == 1) {
            int gr = m0 + row;
            int b = gr / T_;
            int t = gr - b * T_;
            int tp = t ? (t - 1) : 0;
            acur[it]  = ((size_t)b * T_ + t)  * F_ + seg * 8;
            aprev[it] = ((size_t)b * T_ + tp) * F_ + seg * 8;
        } else {
            acur[it] = (size_t)(m0 + row) * H_ + seg * 8;
        }
        boff[it] = (size_t)(n0 + row) * KDIM + seg * 8;
    }

    auto stage = [&](int c, int slot) {
        const int k0 = c * BK;
        uint32_t sA = smbase + slot * SSTR;
        #pragma unroll
        for (int it = 0; it < 2; it++) {
            uint32_t d = st_d0 + it * (64 * ROWB);
            size_t so;
            if (MODE == 1) so = (k0 < 128) ? (aprev[it] + k0) : (acur[it] + (k0 - 128));
            else           so = acur[it] + k0;
            cp16(sA + d,          AH + so);
            cp16(sA + PL + d,     AL + so);
            size_t bo = boff[it] + k0;
            cp16(sA + 2 * PL + d, WH + bo);
            cp16(sA + 3 * PL + d, WL + bo);
        }
    };

    float acc[4][4][4];
    #pragma unroll
    for (int i = 0; i < 4; i++)
        #pragma unroll
        for (int j = 0; j < 4; j++)
            #pragma unroll
            for (int q = 0; q < 4; q++) acc[i][j][q] = 0.f;

    // ldmatrix addressing: swizzle const per thread (i*16/jj*16 preserve (row>>1)&3)
    const uint32_t a_rowb = (uint32_t)(wm * 64) + (lane & 15);
    const uint32_t sw_a   = (a_rowb >> 1) & 3;
    const uint32_t a_half = (uint32_t)lane >> 4;                 // 0/1
    const uint32_t b_rowb = (uint32_t)(wn * 32) + (((uint32_t)lane >> 4) << 3) + (lane & 7);
    const uint32_t sw_b   = (b_rowb >> 1) & 3;
    const uint32_t b_half = ((uint32_t)lane >> 3) & 1;

    stage(0, 0); CP_COMMIT();
    stage(1, 1); CP_COMMIT();

    #pragma unroll 1
    for (int c = 0; c < KDIM / BK; c++) {
        CP_WAIT1();                  // group c complete (c+1 may be in flight)
        __syncthreads();             // all warps done reading slot (c-1)%3
        if (c + 2 < KDIM / BK) stage(c + 2, (c + 2) % NSTAGE);
        CP_COMMIT();

        const int slot = c % NSTAGE;
        const uint32_t sAh = smbase + slot * SSTR;
        const uint32_t sAl = sAh + PL;
        const uint32_t sBh = sAh + 2 * PL;
        const uint32_t sBl = sAh + 3 * PL;

        #pragma unroll
        for (int s = 0; s < 2; s++) {
            const uint32_t a_co = ((2 * s + a_half) ^ sw_a) << 4;
            const uint32_t b_co = ((2 * s + b_half) ^ sw_b) << 4;
            uint32_t bh[4][2], bl[4][2];
            #pragma unroll
            for (int jj = 0; jj < 2; jj++) {
                uint32_t off = (b_rowb + jj * 16) * ROWB + b_co;
                uint32_t r0, r1, r2, r3;
                ldsm_x4(r0, r1, r2, r3, sBh + off);
                bh[2 * jj][0] = r0; bh[2 * jj][1] = r1;
                bh[2 * jj + 1][0] = r2; bh[2 * jj + 1][1] = r3;
                ldsm_x4(r0, r1, r2, r3, sBl + off);
                bl[2 * jj][0] = r0; bl[2 * jj][1] = r1;
                bl[2 * jj + 1][0] = r2; bl[2 * jj + 1][1] = r3;
            }
            #pragma unroll
            for (int i = 0; i < 4; i++) {
                uint32_t off = (a_rowb + i * 16) * ROWB + a_co;
                uint32_t ah[4], al[4];
                ldsm_x4(ah[0], ah[1], ah[2], ah[3], sAh + off);
                ldsm_x4(al[0], al[1], al[2], al[3], sAl + off);
                #pragma unroll
                for (int j = 0; j < 4; j++) {
                    mma_bf16(acc[i][j], ah, bh[j]);
                    mma_bf16(acc[i][j], ah, bl[j]);
                    mma_bf16(acc[i][j], al, bh[j]);
                }
            }
        }
    }

    // ---- epilogue ----
    const int rloc = lane >> 2;
    const int cpair = (lane & 3) * 2;
    #pragma unroll
    for (int i = 0; i < 4; i++) {
        int r0 = m0 + wm * 64 + i * 16 + rloc;
        int r1 = r0 + 8;
        #pragma unroll
        for (int j = 0; j < 4; j++) {
            int ng = n0 + wn * 32 + j * 8 + cpair;
            float2 bb = *(const float2*)&bias[ng];
            float u0 = acc[i][j][0] + bb.x, u1 = acc[i][j][1] + bb.y;
            float u2 = acc[i][j][2] + bb.x, u3 = acc[i][j][3] + bb.y;
            if (MODE == 1) {
                u0 = fmaxf(u0, 0.f); u1 = fmaxf(u1, 0.f);
                u2 = fmaxf(u2, 0.f); u3 = fmaxf(u3, 0.f);
                uint32_t h0, l0, h1, l1;
                cvt_hilo(u0, u1, h0, l0);
                cvt_hilo(u2, u3, h1, l1);
                *(uint32_t*)&g_Hh[(size_t)r0 * H_ + ng] = h0;
                *(uint32_t*)&g_Hl[(size_t)r0 * H_ + ng] = l0;
                *(uint32_t*)&g_Hh[(size_t)r1 * H_ + ng] = h1;
                *(uint32_t*)&g_Hl[(size_t)r1 * H_ + ng] = l1;
            } else {
                bool sp = (blockIdx.x == 2);   // cols [256,384): softplus (delta)
                float uu[4] = {u0, u1, u2, u3};
                float v[4];
                #pragma unroll
                for (int q = 0; q < 4; q++) {
                    float u = uu[q];
                    v[q] = sp ? (__logf(1.f + __expf(-fabsf(u))) + fmaxf(u, 0.f))
                              : (1.f / (1.f + __expf(-u)));
                }
                float2 v0 = {v[0], v[1]}, v1 = {v[2], v[3]};
                *(float2*)&g_act[(size_t)r0 * O_ + ng] = v0;
                *(float2*)&g_act[(size_t)r1 * O_ + ng] = v1;
            }
        }
    }
}

// ---------------------------------------------------------------------------
// Scan stage A: per-chunk composition  (writes [b][c][f], fully coalesced)
// ---------------------------------------------------------------------------
__global__ __launch_bounds__(256) void scan_reduce_kernel() {
    int id = blockIdx.x * blockDim.x + threadIdx.x;
    int f = id & (F_ - 1);
    int c = (id >> 7) & (NC - 1);
    int b = id >> 12;

    const float* actb = g_act + (size_t)(b * T_) * O_;
    const float* Xtb  = g_Xt + (size_t)b * T_ * F_;

    float A = 1.f, Bv = 0.f;
    int t0 = c * CHUNK;
    for (int t = t0; t < t0 + CHUNK; t++) {
        float s = actb[(size_t)t * O_ + f];
        float x = Xtb[(size_t)t * F_ + f];
        float a = 1.f - s;
        A  *= a;
        Bv = a * Bv + s * x;
    }
    g_Ac[id] = A;
    g_Bc[id] = Bv;
}

// ---------------------------------------------------------------------------
// Scan stage B: per-(b,f) chain over NC chunk summaries (coalesced over f)
// ---------------------------------------------------------------------------
__global__ __launch_bounds__(128) void scan_chain_kernel() {
    int b = blockIdx.x, f = threadIdx.x;
    float M = 0.f;
    #pragma unroll
    for (int c = 0; c < NC; c++) {
        int idx = (b * NC + c) * F_ + f;
        g_Ms[idx] = M;
        M = g_Ac[idx] * M + g_Bc[idx];
    }
}

// ---------------------------------------------------------------------------
// Scan stage C: replay + PCEN epilogue; smem transpose for coalesced output
// block = (b*NC + c), 128 threads = f
// ---------------------------------------------------------------------------
__global__ __launch_bounds__(128) void scan_final_kernel(float* __restrict__ out) {
    __shared__ float tile[32][129];
    int bc = blockIdx.x;
    int b = bc >> 5;           // /NC
    int c = bc & (NC - 1);
    int f = threadIdx.x;
    int lane = f & 31, wid = f >> 5;

    const float* actb = g_act + (size_t)(b * T_) * O_;
    const float* Xtb  = g_Xt + (size_t)b * T_ * F_;

    float M = g_Ms[bc * F_ + f];
    int t0 = c * CHUNK, t1 = t0 + CHUNK;
    for (int tb = t0; tb < t1; tb += 32) {
        int nrow = min(32, t1 - tb);
        for (int q = 0; q < nrow; q++) {
            int t = tb + q;
            const float* rowp = actb + (size_t)t * O_;
            float s     = rowp[f];
            float alpha = rowp[128 + f];
            float delta = rowp[256 + f];
            float r     = rowp[384 + f];
            float x = Xtb[(size_t)t * F_ + f];
            M = (1.f - s) * M + s * x;
            float base = x * __powf(M + EPS, -alpha) + delta;
            tile[q][f] = __powf(base, r) - __powf(delta, r);
        }
        __syncthreads();
        #pragma unroll
        for (int ff = wid; ff < 128; ff += 4) {
            if (lane < nrow)
                out[(size_t)(b * F_ + ff) * T_ + tb + lane] = tile[lane][ff];
        }
        __syncthreads();
    }
}

// ---------------------------------------------------------------------------
// Launch
// ---------------------------------------------------------------------------
extern "C" void kernel_launch(void* const* d_in, const int* in_sizes, int n_in,
                              void* d_out, int out_size) {
    const float* X  = (const float*)d_in[0];
    const float* W1 = (const float*)d_in[1];
    const float* b1 = (const float*)d_in[2];
    const float* W2 = (const float*)d_in[3];
    const float* b2 = (const float*)d_in[4];
    float* out = (float*)d_out;

    float *Xt;
    __nv_bfloat16 *Xh, *Xl, *W1h, *W1l, *W2h, *W2l;
    cudaGetSymbolAddress((void**)&Xt,  g_Xt);
    cudaGetSymbolAddress((void**)&Xh,  g_Xh);
    cudaGetSymbolAddress((void**)&Xl,  g_Xl);
    cudaGetSymbolAddress((void**)&W1h, g_W1h);
    cudaGetSymbolAddress((void**)&W1l, g_W1l);
    cudaGetSymbolAddress((void**)&W2h, g_W2h);
    cudaGetSymbolAddress((void**)&W2l, g_W2l);

    // Idempotent host-side attribute set (no stream interaction; capture-safe)
    cudaFuncSetAttribute(gemm_mma<1>, cudaFuncAttributeMaxDynamicSharedMemorySize, SMEM_GEMM);
    cudaFuncSetAttribute(gemm_mma<2>, cudaFuncAttributeMaxDynamicSharedMemorySize, SMEM_GEMM);

    // X [F][T] per batch -> Xt/Xh/Xl [T][F]; W1 [K][H] -> [H][K]; W2 [K][O] -> [O][K]
    transpose_conv<<<dim3(T_ / 32, F_ / 32, B_), dim3(32, 8)>>>(X, Xt, Xh, Xl, F_, T_);
    transpose_conv<<<dim3(H_ / 32, KDIM / 32, 1), dim3(32, 8)>>>(W1, nullptr, W1h, W1l, KDIM, H_);
    transpose_conv<<<dim3(O_ / 32, KDIM / 32, 1), dim3(32, 8)>>>(W2, nullptr, W2h, W2l, KDIM, O_);

    gemm_mma<1><<<dim3(H_ / BN, (B_ * T_) / BM), 256, SMEM_GEMM>>>(b1);   // (2, 1000)
    gemm_mma<2><<<dim3(O_ / BN, (B_ * T_) / BM), 256, SMEM_GEMM>>>(b2);   // (4, 1000)

    scan_reduce_kernel<<<(B_ * F_ * NC) / 256, 256>>>();
    scan_chain_kernel<<<B_, 128>>>();
    scan_final_kernel<<<B_ * NC, 128>>>(out);
}

// round 8
// speedup vs baseline: 4.6163x; 1.4744x over previous
#include <cuda_runtime.h>
#include <cuda_fp16.h>
#include <math.h>
#include <stdint.h>

// Problem constants
#define B_   32
#define F_   128
#define T_   4000
#define H_   256     // hidden
#define O_   512     // 4F
#define KDIM 256     // 2F
#define EPS  1e-6f

// Scan chunking: 32 chunks of 125 -> 4000
#define CHUNK 125
#define NC    32

// GEMM tiling
#define BM 128
#define BN 128
#define BK 32
#define ROWB 64                   // smem row stride bytes (XOR swizzle, no pad)
#define PL   (BM * ROWB)          // one plane: 8192 B
#define SSTR (2 * PL)             // one stage (A, B): 16384 B
#define NSTAGE 4
#define SMEM_GEMM (NSTAGE * SSTR) // 65536 B

// ---------------------------------------------------------------------------
// Scratch (device globals)
// ---------------------------------------------------------------------------
__device__ __align__(128) float   g_Xt [B_ * T_ * F_];   // fp32 for scans
__device__ __align__(128) __half  g_Xf [B_ * T_ * F_];   // fp16 for GEMM1
__device__ __align__(128) __half  g_W1f[H_ * KDIM];
__device__ __align__(128) __half  g_W2f[O_ * KDIM];
__device__ __align__(128) __half  g_Hf [B_ * T_ * H_];
__device__ __align__(128) float   g_act[B_ * T_ * O_];
__device__ float g_Ac[B_ * NC * F_];    // [b][c][f]
__device__ float g_Bc[B_ * NC * F_];
__device__ float g_Ms[B_ * NC * F_];

// ---------------------------------------------------------------------------
// Helpers
// ---------------------------------------------------------------------------
__device__ __forceinline__ uint32_t smem_u32(const void* p) {
    uint32_t a;
    asm("{ .reg .u64 t; cvta.to.shared.u64 t, %1; cvt.u32.u64 %0, t; }" : "=r"(a) : "l"(p));
    return a;
}
__device__ __forceinline__ void cp16(uint32_t dst, const void* src) {
    asm volatile("cp.async.cg.shared.global [%0], [%1], 16;" :: "r"(dst), "l"(src) : "memory");
}
#define CP_COMMIT() asm volatile("cp.async.commit_group;" ::: "memory")
#define CP_WAIT2()  asm volatile("cp.async.wait_group 2;" ::: "memory")

__device__ __forceinline__ void ldsm_x4(uint32_t& r0, uint32_t& r1, uint32_t& r2, uint32_t& r3,
                                        uint32_t addr) {
    asm volatile("ldmatrix.sync.aligned.m8n8.x4.shared.b16 {%0,%1,%2,%3}, [%4];"
                 : "=r"(r0), "=r"(r1), "=r"(r2), "=r"(r3) : "r"(addr));
}
__device__ __forceinline__ void mma_fp16(float* c, const uint32_t* a, const uint32_t* b) {
    asm volatile("mma.sync.aligned.m16n8k16.row.col.f32.f16.f16.f32 "
                 "{%0,%1,%2,%3}, {%4,%5,%6,%7}, {%8,%9}, {%0,%1,%2,%3};"
                 : "+f"(c[0]), "+f"(c[1]), "+f"(c[2]), "+f"(c[3])
                 : "r"(a[0]), "r"(a[1]), "r"(a[2]), "r"(a[3]), "r"(b[0]), "r"(b[1]));
}
__device__ __forceinline__ uint32_t pack_h2(float x, float y) {
    __half2 h = __floats2half2_rn(x, y);
    return *(uint32_t*)&h;
}

// ---------------------------------------------------------------------------
// Transpose + fp16 convert: in [R][C] fp32 -> out [C][R] (fp32 optional, fp16)
// ---------------------------------------------------------------------------
__global__ void transpose_conv(const float* __restrict__ in, float* __restrict__ outF,
                               __half* __restrict__ outH, int R, int C) {
    __shared__ float tile[32][33];
    size_t boff = (size_t)blockIdx.z * R * C;
    in += boff;
    int c0 = blockIdx.x * 32, r0 = blockIdx.y * 32;
    int x = threadIdx.x, y = threadIdx.y;
    #pragma unroll
    for (int i = 0; i < 32; i += 8)
        tile[y + i][x] = in[(size_t)(r0 + y + i) * C + c0 + x];
    __syncthreads();
    #pragma unroll
    for (int i = 0; i < 32; i += 8) {
        float v = tile[x][y + i];
        size_t idx = boff + (size_t)(c0 + y + i) * R + r0 + x;
        if (outF) outF[idx] = v;
        outH[idx] = __float2half_rn(v);
    }
}

// ---------------------------------------------------------------------------
// GEMM via fp16 mma.sync, 4-stage cp.async pipeline, XOR-swizzled smem.
// MODE 1: Hf  = relu(concat(X[:,t-1],X[:,t]) @ W1 + b1)   [128000 x 256]
// MODE 2: act = activation(h @ W2 + b2)                   [128000 x 512]
// ---------------------------------------------------------------------------
template<int MODE>
__global__ __launch_bounds__(256, 2) void gemm_mma(const float* __restrict__ bias) {
    extern __shared__ __align__(128) char sm[];
    const int tid = threadIdx.x;
    const int lane = tid & 31;
    const int wid = tid >> 5;
    const int wm = wid >> 2;
    const int wn = wid & 3;
    const int n0 = blockIdx.x * BN;
    const int m0 = blockIdx.y * BM;

    const uint32_t smbase = smem_u32(sm);

    // staging: thread -> (row0 + it*64, seg); swizzle const across both rows
    const int seg  = tid & 3;
    const int row0 = tid >> 2;
    const uint32_t sw_st = ((uint32_t)row0 >> 1) & 3;
    const uint32_t st_d0 = (uint32_t)row0 * ROWB + ((seg ^ sw_st) << 4);

    const __half* AF = (MODE == 1) ? g_Xf : g_Hf;
    const __half* WF = (MODE == 1) ? g_W1f : g_W2f;

    size_t acur[2], aprev[2], boff[2];
    #pragma unroll
    for (int it = 0; it < 2; it++) {
        int row = row0 + it * 64;
        if (MODE == 1) {
            int gr = m0 + row;
            int b = gr / T_;
            int t = gr - b * T_;
            int tp = t ? (t - 1) : 0;
            acur[it]  = ((size_t)b * T_ + t)  * F_ + seg * 8;
            aprev[it] = ((size_t)b * T_ + tp) * F_ + seg * 8;
        } else {
            acur[it] = (size_t)(m0 + row) * H_ + seg * 8;
        }
        boff[it] = (size_t)(n0 + row) * KDIM + seg * 8;
    }

    auto stage = [&](int c, int slot) {
        const int k0 = c * BK;
        uint32_t sA = smbase + slot * SSTR;
        #pragma unroll
        for (int it = 0; it < 2; it++) {
            uint32_t d = st_d0 + it * (64 * ROWB);
            size_t so;
            if (MODE == 1) so = (k0 < 128) ? (aprev[it] + k0) : (acur[it] + (k0 - 128));
            else           so = acur[it] + k0;
            cp16(sA + d,      AF + so);
            cp16(sA + PL + d, WF + boff[it] + k0);
        }
    };

    float acc[4][4][4];
    #pragma unroll
    for (int i = 0; i < 4; i++)
        #pragma unroll
        for (int j = 0; j < 4; j++)
            #pragma unroll
            for (int q = 0; q < 4; q++) acc[i][j][q] = 0.f;

    // ldmatrix addressing: swizzle const per thread (i*16/jj*16 preserve (row>>1)&3)
    const uint32_t a_rowb = (uint32_t)(wm * 64) + (lane & 15);
    const uint32_t sw_a   = (a_rowb >> 1) & 3;
    const uint32_t a_half = (uint32_t)lane >> 4;                 // 0/1
    const uint32_t b_rowb = (uint32_t)(wn * 32) + (((uint32_t)lane >> 4) << 3) + (lane & 7);
    const uint32_t sw_b   = (b_rowb >> 1) & 3;
    const uint32_t b_half = ((uint32_t)lane >> 3) & 1;

    stage(0, 0); CP_COMMIT();
    stage(1, 1); CP_COMMIT();
    stage(2, 2); CP_COMMIT();

    #pragma unroll 1
    for (int c = 0; c < KDIM / BK; c++) {
        CP_WAIT2();                  // group c complete (c+1, c+2 may be in flight)
        __syncthreads();             // all warps done reading slot (c-1)%4
        if (c + 3 < KDIM / BK) stage(c + 3, (c + 3) % NSTAGE);
        CP_COMMIT();

        const int slot = c % NSTAGE;
        const uint32_t sA = smbase + slot * SSTR;
        const uint32_t sB = sA + PL;

        #pragma unroll
        for (int s = 0; s < 2; s++) {
            const uint32_t a_co = ((2 * s + a_half) ^ sw_a) << 4;
            const uint32_t b_co = ((2 * s + b_half) ^ sw_b) << 4;
            uint32_t bf[4][2];
            #pragma unroll
            for (int jj = 0; jj < 2; jj++) {
                uint32_t off = (b_rowb + jj * 16) * ROWB + b_co;
                uint32_t r0, r1, r2, r3;
                ldsm_x4(r0, r1, r2, r3, sB + off);
                bf[2 * jj][0] = r0; bf[2 * jj][1] = r1;
                bf[2 * jj + 1][0] = r2; bf[2 * jj + 1][1] = r3;
            }
            #pragma unroll
            for (int i = 0; i < 4; i++) {
                uint32_t off = (a_rowb + i * 16) * ROWB + a_co;
                uint32_t af[4];
                ldsm_x4(af[0], af[1], af[2], af[3], sA + off);
                #pragma unroll
                for (int j = 0; j < 4; j++)
                    mma_fp16(acc[i][j], af, bf[j]);
            }
        }
    }

    // ---- epilogue ----
    const int rloc = lane >> 2;
    const int cpair = (lane & 3) * 2;
    #pragma unroll
    for (int i = 0; i < 4; i++) {
        int r0 = m0 + wm * 64 + i * 16 + rloc;
        int r1 = r0 + 8;
        #pragma unroll
        for (int j = 0; j < 4; j++) {
            int ng = n0 + wn * 32 + j * 8 + cpair;
            float2 bb = *(const float2*)&bias[ng];
            float u0 = acc[i][j][0] + bb.x, u1 = acc[i][j][1] + bb.y;
            float u2 = acc[i][j][2] + bb.x, u3 = acc[i][j][3] + bb.y;
            if (MODE == 1) {
                u0 = fmaxf(u0, 0.f); u1 = fmaxf(u1, 0.f);
                u2 = fmaxf(u2, 0.f); u3 = fmaxf(u3, 0.f);
                *(uint32_t*)&g_Hf[(size_t)r0 * H_ + ng] = pack_h2(u0, u1);
                *(uint32_t*)&g_Hf[(size_t)r1 * H_ + ng] = pack_h2(u2, u3);
            } else {
                bool sp = (blockIdx.x == 2);   // cols [256,384): softplus (delta)
                float uu[4] = {u0, u1, u2, u3};
                float v[4];
                #pragma unroll
                for (int q = 0; q < 4; q++) {
                    float u = uu[q];
                    v[q] = sp ? (__logf(1.f + __expf(-fabsf(u))) + fmaxf(u, 0.f))
                              : (1.f / (1.f + __expf(-u)));
                }
                float2 v0 = {v[0], v[1]}, v1 = {v[2], v[3]};
                *(float2*)&g_act[(size_t)r0 * O_ + ng] = v0;
                *(float2*)&g_act[(size_t)r1 * O_ + ng] = v1;
            }
        }
    }
}

// ---------------------------------------------------------------------------
// Scan stage A: per-chunk composition  (writes [b][c][f], fully coalesced)
// ---------------------------------------------------------------------------
__global__ __launch_bounds__(256) void scan_reduce_kernel() {
    int id = blockIdx.x * blockDim.x + threadIdx.x;
    int f = id & (F_ - 1);
    int c = (id >> 7) & (NC - 1);
    int b = id >> 12;

    const float* actb = g_act + (size_t)(b * T_) * O_;
    const float* Xtb  = g_Xt + (size_t)b * T_ * F_;

    float A = 1.f, Bv = 0.f;
    int t0 = c * CHUNK;
    for (int t = t0; t < t0 + CHUNK; t++) {
        float s = actb[(size_t)t * O_ + f];
        float x = Xtb[(size_t)t * F_ + f];
        float a = 1.f - s;
        A  *= a;
        Bv = a * Bv + s * x;
    }
    g_Ac[id] = A;
    g_Bc[id] = Bv;
}

// ---------------------------------------------------------------------------
// Scan stage B: per-(b,f) chain over NC chunk summaries (coalesced over f)
// ---------------------------------------------------------------------------
__global__ __launch_bounds__(128) void scan_chain_kernel() {
    int b = blockIdx.x, f = threadIdx.x;
    float M = 0.f;
    #pragma unroll
    for (int c = 0; c < NC; c++) {
        int idx = (b * NC + c) * F_ + f;
        g_Ms[idx] = M;
        M = g_Ac[idx] * M + g_Bc[idx];
    }
}

// ---------------------------------------------------------------------------
// Scan stage C: replay + PCEN epilogue; smem transpose for coalesced output
// block = (b*NC + c), 128 threads = f
// ---------------------------------------------------------------------------
__global__ __launch_bounds__(128) void scan_final_kernel(float* __restrict__ out) {
    __shared__ float tile[32][129];
    int bc = blockIdx.x;
    int b = bc >> 5;           // /NC
    int c = bc & (NC - 1);
    int f = threadIdx.x;
    int lane = f & 31, wid = f >> 5;

    const float* actb = g_act + (size_t)(b * T_) * O_;
    const float* Xtb  = g_Xt + (size_t)b * T_ * F_;

    float M = g_Ms[bc * F_ + f];
    int t0 = c * CHUNK, t1 = t0 + CHUNK;
    for (int tb = t0; tb < t1; tb += 32) {
        int nrow = min(32, t1 - tb);
        for (int q = 0; q < nrow; q++) {
            int t = tb + q;
            const float* rowp = actb + (size_t)t * O_;
            float s     = rowp[f];
            float alpha = rowp[128 + f];
            float delta = rowp[256 + f];
            float r     = rowp[384 + f];
            float x = Xtb[(size_t)t * F_ + f];
            M = (1.f - s) * M + s * x;
            float base = x * __powf(M + EPS, -alpha) + delta;
            tile[q][f] = __powf(base, r) - __powf(delta, r);
        }
        __syncthreads();
        #pragma unroll
        for (int ff = wid; ff < 128; ff += 4) {
            if (lane < nrow)
                out[(size_t)(b * F_ + ff) * T_ + tb + lane] = tile[lane][ff];
        }
        __syncthreads();
    }
}

// ---------------------------------------------------------------------------
// Launch
// ---------------------------------------------------------------------------
extern "C" void kernel_launch(void* const* d_in, const int* in_sizes, int n_in,
                              void* d_out, int out_size) {
    const float* X  = (const float*)d_in[0];
    const float* W1 = (const float*)d_in[1];
    const float* b1 = (const float*)d_in[2];
    const float* W2 = (const float*)d_in[3];
    const float* b2 = (const float*)d_in[4];
    float* out = (float*)d_out;

    float *Xt;
    __half *Xf, *W1f, *W2f;
    cudaGetSymbolAddress((void**)&Xt,  g_Xt);
    cudaGetSymbolAddress((void**)&Xf,  g_Xf);
    cudaGetSymbolAddress((void**)&W1f, g_W1f);
    cudaGetSymbolAddress((void**)&W2f, g_W2f);

    // Idempotent host-side attribute set (no stream interaction; capture-safe)
    cudaFuncSetAttribute(gemm_mma<1>, cudaFuncAttributeMaxDynamicSharedMemorySize, SMEM_GEMM);
    cudaFuncSetAttribute(gemm_mma<2>, cudaFuncAttributeMaxDynamicSharedMemorySize, SMEM_GEMM);

    // X [F][T] per batch -> Xt/Xf [T][F]; W1 [K][H] -> [H][K]; W2 [K][O] -> [O][K]
    transpose_conv<<<dim3(T_ / 32, F_ / 32, B_), dim3(32, 8)>>>(X, Xt, Xf, F_, T_);
    transpose_conv<<<dim3(H_ / 32, KDIM / 32, 1), dim3(32, 8)>>>(W1, nullptr, W1f, KDIM, H_);
    transpose_conv<<<dim3(O_ / 32, KDIM / 32, 1), dim3(32, 8)>>>(W2, nullptr, W2f, KDIM, O_);

    gemm_mma<1><<<dim3(H_ / BN, (B_ * T_) / BM), 256, SMEM_GEMM>>>(b1);   // (2, 1000)
    gemm_mma<2><<<dim3(O_ / BN, (B_ * T_) / BM), 256, SMEM_GEMM>>>(b2);   // (4, 1000)

    scan_reduce_kernel<<<(B_ * F_ * NC) / 256, 256>>>();
    scan_chain_kernel<<<B_, 128>>>();
    scan_final_kernel<<<B_ * NC, 128>>>(out);
}